// round 16
// baseline (speedup 1.0000x reference)
#include <cuda_runtime.h>
#include <cuda_fp16.h>
#include <cstdint>

// ---------------------------------------------------------------------------
// 2-layer GCN:  out = gcn(relu(gcn(x, W1, b1)), W2, b2)
// gcn(x,W,b)[v] = dis[v] * ( hs[v] + sum_{e: src->v} hs[src] ) + b
//   hs = (x @ W) * dis[row],  dis[v] = rsqrt(1 + indeg(v))
// GEMMs: fp16 mma.sync m16n8k16 + ldmatrix, pre-transposed fp16 weights.
// Aggs: 8-edge unroll, two independent 4-deep fp16 trees, fp32 accum.
// CSR: count stores uint8 slot -> atomic-free fill (8 edges/thread),
// overlapped with gemm1 on a side stream.
// ---------------------------------------------------------------------------

#define NNODES 100000
#define NEDGES 1600000
#define INC 128
#define HIDC 128
#define OUTC 64

// -------------------- scratch (device globals; no runtime alloc) -----------
__device__ int     g_cnt[NNODES + 512];  // counts + lookback state (one memset)
__device__ uint8_t g_slot8[NEDGES];      // per-edge slot within its dst row
__device__ int     g_rowptr[NNODES + 1];
__device__ int     g_csr[NEDGES];
__device__ float   g_dis[NNODES];
__device__ __half  g_w1t[HIDC * INC];    // W1^T fp16 [n][k]
__device__ __half  g_w2t[OUTC * HIDC];   // W2^T fp16 [n][k]
__device__ __half  g_hs1[(size_t)NNODES * HIDC];
__device__ __half  g_x2 [(size_t)NNODES * HIDC];
__device__ __half  g_hs2[(size_t)NNODES * OUTC];

#define SCAN_AGG 0x40000000u
#define SCAN_PRE 0x80000000u
#define SCAN_VAL 0x3FFFFFFFu

// -------------------- mma / ldmatrix helpers --------------------------------
__device__ __forceinline__ void mma_f16(float* c, const uint32_t* a,
                                        uint32_t b0, uint32_t b1) {
    asm volatile(
        "mma.sync.aligned.m16n8k16.row.col.f32.f16.f16.f32 "
        "{%0,%1,%2,%3}, {%4,%5,%6,%7}, {%8,%9}, {%0,%1,%2,%3};"
        : "+f"(c[0]), "+f"(c[1]), "+f"(c[2]), "+f"(c[3])
        : "r"(a[0]), "r"(a[1]), "r"(a[2]), "r"(a[3]), "r"(b0), "r"(b1));
}

#define LDSM4(r, addr) \
    asm volatile("ldmatrix.sync.aligned.m8n8.x4.shared.b16 {%0,%1,%2,%3}, [%4];" \
                 : "=r"((r)[0]), "=r"((r)[1]), "=r"((r)[2]), "=r"((r)[3])       \
                 : "r"(addr))

// -------------------- weight transpose (once): fp32 [k][n] -> fp16 [n][k] --
__global__ void k_wt(const float* __restrict__ W1, const float* __restrict__ W2) {
    int idx = blockIdx.x * 256 + threadIdx.x;       // 0..12287
    if (idx < 8192) {                               // W1: 128x128
        int nn = idx & 127, kp = idx >> 7;
        float w0 = W1[(size_t)(2 * kp)     * 128 + nn];
        float w1 = W1[(size_t)(2 * kp + 1) * 128 + nn];
        *(__half2*)(g_w1t + nn * 128 + 2 * kp) = __floats2half2_rn(w0, w1);
    } else {                                        // W2: 128x64
        int j = idx - 8192;
        int nn = j & 63, kp = j >> 6;
        float w0 = W2[(size_t)(2 * kp)     * 64 + nn];
        float w1 = W2[(size_t)(2 * kp + 1) * 64 + nn];
        *(__half2*)(g_w2t + nn * 128 + 2 * kp) = __floats2half2_rn(w0, w1);
    }
}

// -------------------- CSR: histogram + per-edge uint8 slot ------------------
__global__ void k_count(const int* __restrict__ dst, int e) {
    int i4 = (blockIdx.x * blockDim.x + threadIdx.x) * 4;
    if (i4 + 3 < e) {
        int4 d = *(const int4*)(dst + i4);
        uchar4 sl;
        sl.x = (uint8_t)atomicAdd(&g_cnt[d.x], 1);
        sl.y = (uint8_t)atomicAdd(&g_cnt[d.y], 1);
        sl.z = (uint8_t)atomicAdd(&g_cnt[d.z], 1);
        sl.w = (uint8_t)atomicAdd(&g_cnt[d.w], 1);
        *(uchar4*)(g_slot8 + i4) = sl;
    } else {
        for (int j = i4; j < e; j++)
            g_slot8[j] = (uint8_t)atomicAdd(&g_cnt[dst[j]], 1);
    }
}

// -------------------- CSR: single-pass scan (decoupled lookback) -----------
__global__ void __launch_bounds__(256)
k_scan_lb(int n, int nb) {
    __shared__ int warpsum[8];
    __shared__ int sh_total, sh_pref;
    const int b    = blockIdx.x;
    const int tid  = threadIdx.x;
    const int lane = tid & 31;
    const int w    = tid >> 5;
    const int idx  = b * 256 + tid;
    unsigned* st = (unsigned*)(g_cnt + NNODES);

    int x = (idx < n) ? g_cnt[idx] : 0;
    if (idx < n) g_dis[idx] = rsqrtf((float)(x + 1));

    int incl = x;
    #pragma unroll
    for (int o = 1; o < 32; o <<= 1) {
        int t = __shfl_up_sync(0xffffffffu, incl, o);
        if (lane >= o) incl += t;
    }
    if (lane == 31) warpsum[w] = incl;
    __syncthreads();
    if (w == 0) {
        int s = (lane < 8) ? warpsum[lane] : 0;
        #pragma unroll
        for (int o = 1; o < 8; o <<= 1) {
            int t = __shfl_up_sync(0xffffffffu, s, o);
            if (lane >= o) s += t;
        }
        if (lane < 8) warpsum[lane] = s;
    }
    __syncthreads();
    if (w > 0) incl += warpsum[w - 1];

    if (tid == 255) sh_total = incl;
    __syncthreads();

    if (tid == 255) {
        unsigned v = ((b == 0) ? SCAN_PRE : SCAN_AGG) | (unsigned)sh_total;
        __threadfence();
        atomicExch(&st[b], v);
    }
    if (tid == 0) {
        int run = 0;
        if (b > 0) {
            int p = b - 1;
            while (true) {
                unsigned s;
                do { s = atomicAdd(&st[p], 0u); } while ((s >> 30) == 0u);
                run += (int)(s & SCAN_VAL);
                if (s & SCAN_PRE) break;
                p--;
            }
            __threadfence();
            atomicExch(&st[b], SCAN_PRE | (unsigned)(run + sh_total));
        }
        sh_pref = run;
    }
    __syncthreads();

    int pre = sh_pref;
    if (idx < n) g_rowptr[idx] = pre + incl - x;
    if (idx == n - 1) g_rowptr[n] = pre + incl;
}

// -------------------- CSR: fill (atomic-free, 8 edges/thread) --------------
__global__ void k_fill(const int* __restrict__ src, const int* __restrict__ dst, int e) {
    int i8 = (blockIdx.x * blockDim.x + threadIdx.x) * 8;
    if (i8 + 7 < e) {
        int4 d0 = *(const int4*)(dst + i8);
        int4 d1 = *(const int4*)(dst + i8 + 4);
        int4 s0 = *(const int4*)(src + i8);
        int4 s1 = *(const int4*)(src + i8 + 4);
        uint2 slp = *(const uint2*)(g_slot8 + i8);
        uint8_t* sl = (uint8_t*)&slp;
        g_csr[g_rowptr[d0.x] + sl[0]] = s0.x;
        g_csr[g_rowptr[d0.y] + sl[1]] = s0.y;
        g_csr[g_rowptr[d0.z] + sl[2]] = s0.z;
        g_csr[g_rowptr[d0.w] + sl[3]] = s0.w;
        g_csr[g_rowptr[d1.x] + sl[4]] = s1.x;
        g_csr[g_rowptr[d1.y] + sl[5]] = s1.y;
        g_csr[g_rowptr[d1.z] + sl[6]] = s1.z;
        g_csr[g_rowptr[d1.w] + sl[7]] = s1.w;
    } else {
        for (int j = i8; j < e; j++)
            g_csr[g_rowptr[dst[j]] + (int)g_slot8[j]] = src[j];
    }
}

// -------------------- GEMM 1 (fp16 mma + ldmatrix): hs1 = (X@W1)*dis -------
#define SH_STRIDE 136
#define G1_SMEM ((128 * SH_STRIDE + 128 * SH_STRIDE) * 2)

__global__ void __launch_bounds__(256)
k_gemm1_mma(const float* __restrict__ X, int m) {
    extern __shared__ __half sh[];
    __half* As = sh;                       // [128][136]
    __half* Bs = sh + 128 * SH_STRIDE;     // [128][136]
    const int tid  = threadIdx.x;
    const int lane = tid & 31;
    const int wid  = tid >> 5;
    const int gr   = lane >> 2;
    const int gc   = lane & 3;
    const int bm   = blockIdx.x * 128;
    const int m0   = (wid & 3) * 32;
    const int n0   = (wid >> 2) * 64;

    #pragma unroll
    for (int i = 0; i < 8; i++) {
        int f = tid + i * 256;
        int r = f >> 4, c8 = (f & 15) * 8;
        float4 v0 = make_float4(0.f, 0.f, 0.f, 0.f);
        float4 v1 = v0;
        if (bm + r < m) {
            const float* xp = X + (size_t)(bm + r) * 128 + c8;
            v0 = *(const float4*)(xp);
            v1 = *(const float4*)(xp + 4);
        }
        __half2 h0 = __floats2half2_rn(v0.x, v0.y);
        __half2 h1 = __floats2half2_rn(v0.z, v0.w);
        __half2 h2 = __floats2half2_rn(v1.x, v1.y);
        __half2 h3 = __floats2half2_rn(v1.z, v1.w);
        uint4 u;
        u.x = *(uint32_t*)&h0; u.y = *(uint32_t*)&h1;
        u.z = *(uint32_t*)&h2; u.w = *(uint32_t*)&h3;
        *(uint4*)(As + r * SH_STRIDE + c8) = u;
    }
    #pragma unroll
    for (int i = 0; i < 8; i++) {
        int f = tid + i * 256;
        int r = f >> 4, c8 = (f & 15) * 8;
        *(uint4*)(Bs + r * SH_STRIDE + c8) = *(const uint4*)(g_w1t + r * 128 + c8);
    }
    __syncthreads();

    const uint32_t as_b = (uint32_t)__cvta_generic_to_shared(As);
    const uint32_t bs_b = (uint32_t)__cvta_generic_to_shared(Bs);
    const uint32_t a_row  = (uint32_t)(m0 + (lane & 15));
    const uint32_t a_koff = (uint32_t)((lane >> 4) << 3);
    const uint32_t a_ad0  = as_b + (a_row * SH_STRIDE + a_koff) * 2;
    const uint32_t a_ad1  = a_ad0 + 16 * SH_STRIDE * 2;
    const uint32_t b_row  = (uint32_t)(n0 + ((lane >> 4) << 3) + (lane & 7));
    const uint32_t b_koff = (uint32_t)(((lane >> 3) & 1) << 3);
    uint32_t b_ad[4];
    #pragma unroll
    for (int q = 0; q < 4; q++)
        b_ad[q] = bs_b + ((b_row + 16 * q) * SH_STRIDE + b_koff) * 2;

    float acc[2][8][4];
    #pragma unroll
    for (int a = 0; a < 2; a++)
        #pragma unroll
        for (int j = 0; j < 8; j++)
            #pragma unroll
            for (int q = 0; q < 4; q++) acc[a][j][q] = 0.f;

    #pragma unroll
    for (int ks = 0; ks < 8; ks++) {
        const uint32_t kb2 = ks * 32;
        uint32_t a0[4], a1[4], bq[4][4];
        LDSM4(a0, a_ad0 + kb2);
        LDSM4(a1, a_ad1 + kb2);
        #pragma unroll
        for (int q = 0; q < 4; q++) LDSM4(bq[q], b_ad[q] + kb2);
        #pragma unroll
        for (int j = 0; j < 8; j++) {
            int q = j >> 1, h = (j & 1) * 2;
            mma_f16(acc[0][j], a0, bq[q][h], bq[q][h + 1]);
            mma_f16(acc[1][j], a1, bq[q][h], bq[q][h + 1]);
        }
    }

    #pragma unroll
    for (int mf = 0; mf < 2; mf++) {
        int r0 = bm + m0 + mf * 16 + gr;
        int r1 = r0 + 8;
        float d0 = (r0 < m) ? g_dis[r0] : 0.f;
        float d1 = (r1 < m) ? g_dis[r1] : 0.f;
        #pragma unroll
        for (int j = 0; j < 8; j++) {
            int col = n0 + j * 8 + gc * 2;
            if (r0 < m)
                *(__half2*)(g_hs1 + (size_t)r0 * 128 + col) =
                    __floats2half2_rn(acc[mf][j][0] * d0, acc[mf][j][1] * d0);
            if (r1 < m)
                *(__half2*)(g_hs1 + (size_t)r1 * 128 + col) =
                    __floats2half2_rn(acc[mf][j][2] * d1, acc[mf][j][3] * d1);
        }
    }
}

// -------------------- GEMM 2 (fp16 mma + ldmatrix): hs2 = (x2@W2)*dis ------
#define G2_SMEM ((128 * SH_STRIDE + 64 * SH_STRIDE) * 2)

__global__ void __launch_bounds__(256)
k_gemm2_mma(int m) {
    extern __shared__ __half sh[];
    __half* As = sh;                       // [128][136]
    __half* Bs = sh + 128 * SH_STRIDE;     // [64][136]
    const int tid  = threadIdx.x;
    const int lane = tid & 31;
    const int wid  = tid >> 5;
    const int gr   = lane >> 2;
    const int gc   = lane & 3;
    const int bm   = blockIdx.x * 128;
    const int m0   = (wid & 3) * 32;
    const int n0   = (wid >> 2) * 32;

    #pragma unroll
    for (int i = 0; i < 8; i++) {
        int f = tid + i * 256;
        int r = f >> 4, c8 = (f & 15) * 8;
        uint4 v = make_uint4(0u, 0u, 0u, 0u);
        if (bm + r < m) v = *(const uint4*)(g_x2 + (size_t)(bm + r) * 128 + c8);
        *(uint4*)(As + r * SH_STRIDE + c8) = v;
    }
    #pragma unroll
    for (int i = 0; i < 4; i++) {
        int f = tid + i * 256;
        int r = f >> 4, c8 = (f & 15) * 8;
        *(uint4*)(Bs + r * SH_STRIDE + c8) = *(const uint4*)(g_w2t + r * 128 + c8);
    }
    __syncthreads();

    const uint32_t as_b = (uint32_t)__cvta_generic_to_shared(As);
    const uint32_t bs_b = (uint32_t)__cvta_generic_to_shared(Bs);
    const uint32_t a_row  = (uint32_t)(m0 + (lane & 15));
    const uint32_t a_koff = (uint32_t)((lane >> 4) << 3);
    const uint32_t a_ad0  = as_b + (a_row * SH_STRIDE + a_koff) * 2;
    const uint32_t a_ad1  = a_ad0 + 16 * SH_STRIDE * 2;
    const uint32_t b_row  = (uint32_t)(n0 + ((lane >> 4) << 3) + (lane & 7));
    const uint32_t b_koff = (uint32_t)(((lane >> 3) & 1) << 3);
    uint32_t b_ad[2];
    #pragma unroll
    for (int q = 0; q < 2; q++)
        b_ad[q] = bs_b + ((b_row + 16 * q) * SH_STRIDE + b_koff) * 2;

    float acc[2][4][4];
    #pragma unroll
    for (int a = 0; a < 2; a++)
        #pragma unroll
        for (int j = 0; j < 4; j++)
            #pragma unroll
            for (int q = 0; q < 4; q++) acc[a][j][q] = 0.f;

    #pragma unroll
    for (int ks = 0; ks < 8; ks++) {
        const uint32_t kb2 = ks * 32;
        uint32_t a0[4], a1[4], bq[2][4];
        LDSM4(a0, a_ad0 + kb2);
        LDSM4(a1, a_ad1 + kb2);
        #pragma unroll
        for (int q = 0; q < 2; q++) LDSM4(bq[q], b_ad[q] + kb2);
        #pragma unroll
        for (int j = 0; j < 4; j++) {
            int q = j >> 1, h = (j & 1) * 2;
            mma_f16(acc[0][j], a0, bq[q][h], bq[q][h + 1]);
            mma_f16(acc[1][j], a1, bq[q][h], bq[q][h + 1]);
        }
    }

    #pragma unroll
    for (int mf = 0; mf < 2; mf++) {
        int r0 = bm + m0 + mf * 16 + gr;
        int r1 = r0 + 8;
        float d0 = (r0 < m) ? g_dis[r0] : 0.f;
        float d1 = (r1 < m) ? g_dis[r1] : 0.f;
        #pragma unroll
        for (int j = 0; j < 4; j++) {
            int col = n0 + j * 8 + gc * 2;
            if (r0 < m)
                *(__half2*)(g_hs2 + (size_t)r0 * 64 + col) =
                    __floats2half2_rn(acc[mf][j][0] * d0, acc[mf][j][1] * d0);
            if (r1 < m)
                *(__half2*)(g_hs2 + (size_t)r1 * 64 + col) =
                    __floats2half2_rn(acc[mf][j][2] * d1, acc[mf][j][3] * d1);
        }
    }
}

// -------------------- Aggregation 1: x2 = relu(dis*(hs1[v]+sum)+b1) --------
// warp per node; 8-edge unroll = two independent 4-deep fp16 trees (MLP 8).
__global__ void k_agg1(const float* __restrict__ b1, int n) {
    int v = (blockIdx.x * blockDim.x + threadIdx.x) >> 5;
    if (v >= n) return;
    int lane = threadIdx.x & 31;
    int c = lane * 4;
    int s0 = g_rowptr[v], s1 = g_rowptr[v + 1];

    const __half* base = g_hs1 + c;
    uint2 us = *(const uint2*)(base + (size_t)v * 128);
    float2 f01 = __half22float2(*(__half2*)&us.x);
    float2 f23 = __half22float2(*(__half2*)&us.y);
    float4 acc0 = make_float4(f01.x, f01.y, f23.x, f23.y);
    float4 acc1 = make_float4(0.f, 0.f, 0.f, 0.f);

    for (int j = s0; j < s1; j += 32) {
        int mm = s1 - j; if (mm > 32) mm = 32;
        int sv = (lane < mm) ? g_csr[j + lane] : 0;
        int t = 0;
        for (; t + 7 < mm; t += 8) {
            int i0 = __shfl_sync(0xffffffffu, sv, t);
            int i1 = __shfl_sync(0xffffffffu, sv, t + 1);
            int i2 = __shfl_sync(0xffffffffu, sv, t + 2);
            int i3 = __shfl_sync(0xffffffffu, sv, t + 3);
            int i4 = __shfl_sync(0xffffffffu, sv, t + 4);
            int i5 = __shfl_sync(0xffffffffu, sv, t + 5);
            int i6 = __shfl_sync(0xffffffffu, sv, t + 6);
            int i7 = __shfl_sync(0xffffffffu, sv, t + 7);
            uint2 u0 = *(const uint2*)(base + (size_t)i0 * 128);
            uint2 u1 = *(const uint2*)(base + (size_t)i1 * 128);
            uint2 u2 = *(const uint2*)(base + (size_t)i2 * 128);
            uint2 u3 = *(const uint2*)(base + (size_t)i3 * 128);
            uint2 u4 = *(const uint2*)(base + (size_t)i4 * 128);
            uint2 u5 = *(const uint2*)(base + (size_t)i5 * 128);
            uint2 u6 = *(const uint2*)(base + (size_t)i6 * 128);
            uint2 u7 = *(const uint2*)(base + (size_t)i7 * 128);
            __half2 qa0 = __hadd2(__hadd2(*(__half2*)&u0.x, *(__half2*)&u1.x),
                                  __hadd2(*(__half2*)&u2.x, *(__half2*)&u3.x));
            __half2 qa1 = __hadd2(__hadd2(*(__half2*)&u0.y, *(__half2*)&u1.y),
                                  __hadd2(*(__half2*)&u2.y, *(__half2*)&u3.y));
            __half2 qb0 = __hadd2(__hadd2(*(__half2*)&u4.x, *(__half2*)&u5.x),
                                  __hadd2(*(__half2*)&u6.x, *(__half2*)&u7.x));
            __half2 qb1 = __hadd2(__hadd2(*(__half2*)&u4.y, *(__half2*)&u5.y),
                                  __hadd2(*(__half2*)&u6.y, *(__half2*)&u7.y));
            float2 a0 = __half22float2(qa0);
            float2 a1 = __half22float2(qa1);
            float2 b0 = __half22float2(qb0);
            float2 b1v = __half22float2(qb1);
            acc0.x += a0.x; acc0.y += a0.y; acc0.z += a1.x; acc0.w += a1.y;
            acc1.x += b0.x; acc1.y += b0.y; acc1.z += b1v.x; acc1.w += b1v.y;
        }
        if (t + 3 < mm) {
            int i0 = __shfl_sync(0xffffffffu, sv, t);
            int i1 = __shfl_sync(0xffffffffu, sv, t + 1);
            int i2 = __shfl_sync(0xffffffffu, sv, t + 2);
            int i3 = __shfl_sync(0xffffffffu, sv, t + 3);
            uint2 u0 = *(const uint2*)(base + (size_t)i0 * 128);
            uint2 u1 = *(const uint2*)(base + (size_t)i1 * 128);
            uint2 u2 = *(const uint2*)(base + (size_t)i2 * 128);
            uint2 u3 = *(const uint2*)(base + (size_t)i3 * 128);
            __half2 q0 = __hadd2(__hadd2(*(__half2*)&u0.x, *(__half2*)&u1.x),
                                 __hadd2(*(__half2*)&u2.x, *(__half2*)&u3.x));
            __half2 q1 = __hadd2(__hadd2(*(__half2*)&u0.y, *(__half2*)&u1.y),
                                 __hadd2(*(__half2*)&u2.y, *(__half2*)&u3.y));
            float2 a0 = __half22float2(q0);
            float2 a1 = __half22float2(q1);
            acc0.x += a0.x; acc0.y += a0.y; acc0.z += a1.x; acc0.w += a1.y;
            t += 4;
        }
        if (t + 1 < mm) {
            int i0 = __shfl_sync(0xffffffffu, sv, t);
            int i1 = __shfl_sync(0xffffffffu, sv, t + 1);
            uint2 u0 = *(const uint2*)(base + (size_t)i0 * 128);
            uint2 u1 = *(const uint2*)(base + (size_t)i1 * 128);
            __half2 p0 = __hadd2(*(__half2*)&u0.x, *(__half2*)&u1.x);
            __half2 p1 = __hadd2(*(__half2*)&u0.y, *(__half2*)&u1.y);
            float2 a0 = __half22float2(p0);
            float2 a1 = __half22float2(p1);
            acc0.x += a0.x; acc0.y += a0.y; acc0.z += a1.x; acc0.w += a1.y;
            t += 2;
        }
        if (t < mm) {
            int i0 = __shfl_sync(0xffffffffu, sv, t);
            uint2 u0 = *(const uint2*)(base + (size_t)i0 * 128);
            float2 a = __half22float2(*(__half2*)&u0.x);
            float2 b = __half22float2(*(__half2*)&u0.y);
            acc0.x += a.x; acc0.y += a.y; acc0.z += b.x; acc0.w += b.y;
        }
    }
    float dv = g_dis[v];
    float4 bb = *(const float4*)(b1 + c);
    float ox = fmaxf(fmaf(dv, acc0.x + acc1.x, bb.x), 0.f);
    float oy = fmaxf(fmaf(dv, acc0.y + acc1.y, bb.y), 0.f);
    float oz = fmaxf(fmaf(dv, acc0.z + acc1.z, bb.z), 0.f);
    float ow = fmaxf(fmaf(dv, acc0.w + acc1.w, bb.w), 0.f);
    __half2 h01 = __floats2half2_rn(ox, oy);
    __half2 h23 = __floats2half2_rn(oz, ow);
    uint2 pk;
    pk.x = *(uint32_t*)&h01;
    pk.y = *(uint32_t*)&h23;
    *(uint2*)(g_x2 + (size_t)v * 128 + c) = pk;
}

// -------------------- Aggregation 2: out = dis*(hs2[v]+sum)+b2 -------------
__global__ void k_agg2(const float* __restrict__ b2, float* __restrict__ out, int n) {
    int v = (blockIdx.x * blockDim.x + threadIdx.x) >> 5;
    if (v >= n) return;
    int lane = threadIdx.x & 31;
    int c = lane * 2;
    int s0 = g_rowptr[v], s1 = g_rowptr[v + 1];

    const __half* base = g_hs2 + c;
    float2 acc0 = __half22float2(*(const __half2*)(base + (size_t)v * 64));
    float2 acc1 = make_float2(0.f, 0.f);

    for (int j = s0; j < s1; j += 32) {
        int mm = s1 - j; if (mm > 32) mm = 32;
        int sv = (lane < mm) ? g_csr[j + lane] : 0;
        int t = 0;
        for (; t + 7 < mm; t += 8) {
            int i0 = __shfl_sync(0xffffffffu, sv, t);
            int i1 = __shfl_sync(0xffffffffu, sv, t + 1);
            int i2 = __shfl_sync(0xffffffffu, sv, t + 2);
            int i3 = __shfl_sync(0xffffffffu, sv, t + 3);
            int i4 = __shfl_sync(0xffffffffu, sv, t + 4);
            int i5 = __shfl_sync(0xffffffffu, sv, t + 5);
            int i6 = __shfl_sync(0xffffffffu, sv, t + 6);
            int i7 = __shfl_sync(0xffffffffu, sv, t + 7);
            __half2 h0 = *(const __half2*)(base + (size_t)i0 * 64);
            __half2 h1 = *(const __half2*)(base + (size_t)i1 * 64);
            __half2 h2 = *(const __half2*)(base + (size_t)i2 * 64);
            __half2 h3 = *(const __half2*)(base + (size_t)i3 * 64);
            __half2 h4 = *(const __half2*)(base + (size_t)i4 * 64);
            __half2 h5 = *(const __half2*)(base + (size_t)i5 * 64);
            __half2 h6 = *(const __half2*)(base + (size_t)i6 * 64);
            __half2 h7 = *(const __half2*)(base + (size_t)i7 * 64);
            __half2 qa = __hadd2(__hadd2(h0, h1), __hadd2(h2, h3));
            __half2 qb = __hadd2(__hadd2(h4, h5), __hadd2(h6, h7));
            float2 a0 = __half22float2(qa);
            float2 b0 = __half22float2(qb);
            acc0.x += a0.x; acc0.y += a0.y;
            acc1.x += b0.x; acc1.y += b0.y;
        }
        if (t + 3 < mm) {
            int i0 = __shfl_sync(0xffffffffu, sv, t);
            int i1 = __shfl_sync(0xffffffffu, sv, t + 1);
            int i2 = __shfl_sync(0xffffffffu, sv, t + 2);
            int i3 = __shfl_sync(0xffffffffu, sv, t + 3);
            __half2 h0 = *(const __half2*)(base + (size_t)i0 * 64);
            __half2 h1 = *(const __half2*)(base + (size_t)i1 * 64);
            __half2 h2 = *(const __half2*)(base + (size_t)i2 * 64);
            __half2 h3 = *(const __half2*)(base + (size_t)i3 * 64);
            __half2 q = __hadd2(__hadd2(h0, h1), __hadd2(h2, h3));
            float2 a0 = __half22float2(q);
            acc0.x += a0.x; acc0.y += a0.y;
            t += 4;
        }
        if (t + 1 < mm) {
            int i0 = __shfl_sync(0xffffffffu, sv, t);
            int i1 = __shfl_sync(0xffffffffu, sv, t + 1);
            __half2 h0 = *(const __half2*)(base + (size_t)i0 * 64);
            __half2 h1 = *(const __half2*)(base + (size_t)i1 * 64);
            float2 a0 = __half22float2(__hadd2(h0, h1));
            acc0.x += a0.x; acc0.y += a0.y;
            t += 2;
        }
        if (t < mm) {
            int i0 = __shfl_sync(0xffffffffu, sv, t);
            float2 h0 = __half22float2(*(const __half2*)(base + (size_t)i0 * 64));
            acc0.x += h0.x; acc0.y += h0.y;
        }
    }
    float dv = g_dis[v];
    float2 bb = *(const float2*)(b2 + c);
    float2 o;
    o.x = fmaf(dv, acc0.x + acc1.x, bb.x);
    o.y = fmaf(dv, acc0.y + acc1.y, bb.y);
    *(float2*)(out + (size_t)v * 64 + c) = o;
}

// -------------------- launch ------------------------------------------------
extern "C" void kernel_launch(void* const* d_in, const int* in_sizes, int n_in,
                              void* d_out, int out_size) {
    const float* x  = (const float*)d_in[0];
    const int*   ei = (const int*)d_in[1];
    const float* W1 = (const float*)d_in[2];
    const float* b1 = (const float*)d_in[3];
    const float* W2 = (const float*)d_in[4];
    const float* b2 = (const float*)d_in[5];
    float* out = (float*)d_out;

    const int n = in_sizes[0] / INC;   // 100000
    const int e = in_sizes[1] / 2;     // 1600000
    const int* src = ei;
    const int* dst = ei + e;

    const int nb_n  = (n + 255) / 256;    // scan blocks (391)
    const int nb_e4 = (e + 1023) / 1024;  // 4-edge/thread blocks
    const int nb_e8 = (e + 2047) / 2048;  // 8-edge/thread blocks

    static cudaStream_t s_side = nullptr;
    static cudaEvent_t ev_start = nullptr, ev_wt = nullptr,
                       ev_fork = nullptr, ev_join = nullptr;
    if (!s_side) {
        cudaStreamCreateWithFlags(&s_side, cudaStreamNonBlocking);
        cudaEventCreateWithFlags(&ev_start, cudaEventDisableTiming);
        cudaEventCreateWithFlags(&ev_wt,    cudaEventDisableTiming);
        cudaEventCreateWithFlags(&ev_fork,  cudaEventDisableTiming);
        cudaEventCreateWithFlags(&ev_join,  cudaEventDisableTiming);
        cudaFuncSetAttribute(k_gemm1_mma,
                             cudaFuncAttributeMaxDynamicSharedMemorySize, G1_SMEM);
        cudaFuncSetAttribute(k_gemm2_mma,
                             cudaFuncAttributeMaxDynamicSharedMemorySize, G2_SMEM);
    }

    // side stream: weight transpose overlapped with memset/count
    cudaEventRecord(ev_start, 0);
    cudaStreamWaitEvent(s_side, ev_start, 0);
    k_wt<<<48, 256, 0, s_side>>>(W1, W2);
    cudaEventRecord(ev_wt, s_side);

    // main: zero counts+states -> histogram(+slots) -> scan
    void* cnt_addr = nullptr;
    cudaGetSymbolAddress(&cnt_addr, g_cnt);
    cudaMemsetAsync(cnt_addr, 0, (size_t)(n + 512) * sizeof(int));
    k_count<<<nb_e4, 256>>>(dst, e);
    k_scan_lb<<<nb_n, 256>>>(n, nb_n);

    // fork: atomic-free CSR fill on side stream overlapped with gemm1
    cudaEventRecord(ev_fork, 0);
    cudaStreamWaitEvent(s_side, ev_fork, 0);
    k_fill<<<nb_e8, 256, 0, s_side>>>(src, dst, e);
    cudaEventRecord(ev_join, s_side);

    cudaStreamWaitEvent(0, ev_wt, 0);
    k_gemm1_mma<<<(n + 127) / 128, 256, G1_SMEM>>>(x, n);
    cudaStreamWaitEvent(0, ev_join, 0);

    k_agg1<<<(n + 7) / 8, 256>>>(b1, n);
    k_gemm2_mma<<<(n + 127) / 128, 256, G2_SMEM>>>(n);
    k_agg2<<<(n + 7) / 8, 256>>>(b2, out, n);
}

// round 17
// speedup vs baseline: 1.0944x; 1.0944x over previous
#include <cuda_runtime.h>
#include <cuda_fp16.h>
#include <cstdint>

// ---------------------------------------------------------------------------
// 2-layer GCN:  out = gcn(relu(gcn(x, W1, b1)), W2, b2)
// gcn(x,W,b)[v] = dis[v] * ( hs[v] + sum_{e: src->v} hs[src] ) + b
//   hs = (x @ W) * dis[row],  dis[v] = rsqrt(1 + indeg(v))
// GEMMs: fp16 mma.sync m16n8k16 + ldmatrix, pre-transposed fp16 weights.
// Aggs: standalone (high occupancy), 4-deep fp16 tree pre-add, fp32 accum.
// CSR: count stores uint8 per-edge slot -> atomic-free fill (4 edges/thread),
// overlapped with gemm1 on a side stream.  (= R15 best + uint8 slots only)
// ---------------------------------------------------------------------------

#define NNODES 100000
#define NEDGES 1600000
#define INC 128
#define HIDC 128
#define OUTC 64

// -------------------- scratch (device globals; no runtime alloc) -----------
__device__ int     g_cnt[NNODES + 512];  // counts + lookback state (one memset)
__device__ uint8_t g_slot8[NEDGES];      // per-edge slot within its dst row
__device__ int     g_rowptr[NNODES + 1];
__device__ int     g_csr[NEDGES];
__device__ float   g_dis[NNODES];
__device__ __half  g_w1t[HIDC * INC];    // W1^T fp16 [n][k]
__device__ __half  g_w2t[OUTC * HIDC];   // W2^T fp16 [n][k]
__device__ __half  g_hs1[(size_t)NNODES * HIDC];
__device__ __half  g_x2 [(size_t)NNODES * HIDC];
__device__ __half  g_hs2[(size_t)NNODES * OUTC];

#define SCAN_AGG 0x40000000u
#define SCAN_PRE 0x80000000u
#define SCAN_VAL 0x3FFFFFFFu

// -------------------- mma / ldmatrix helpers --------------------------------
__device__ __forceinline__ void mma_f16(float* c, const uint32_t* a,
                                        uint32_t b0, uint32_t b1) {
    asm volatile(
        "mma.sync.aligned.m16n8k16.row.col.f32.f16.f16.f32 "
        "{%0,%1,%2,%3}, {%4,%5,%6,%7}, {%8,%9}, {%0,%1,%2,%3};"
        : "+f"(c[0]), "+f"(c[1]), "+f"(c[2]), "+f"(c[3])
        : "r"(a[0]), "r"(a[1]), "r"(a[2]), "r"(a[3]), "r"(b0), "r"(b1));
}

#define LDSM4(r, addr) \
    asm volatile("ldmatrix.sync.aligned.m8n8.x4.shared.b16 {%0,%1,%2,%3}, [%4];" \
                 : "=r"((r)[0]), "=r"((r)[1]), "=r"((r)[2]), "=r"((r)[3])       \
                 : "r"(addr))

// -------------------- weight transpose (once): fp32 [k][n] -> fp16 [n][k] --
__global__ void k_wt(const float* __restrict__ W1, const float* __restrict__ W2) {
    int idx = blockIdx.x * 256 + threadIdx.x;       // 0..12287
    if (idx < 8192) {                               // W1: 128x128
        int nn = idx & 127, kp = idx >> 7;
        float w0 = W1[(size_t)(2 * kp)     * 128 + nn];
        float w1 = W1[(size_t)(2 * kp + 1) * 128 + nn];
        *(__half2*)(g_w1t + nn * 128 + 2 * kp) = __floats2half2_rn(w0, w1);
    } else {                                        // W2: 128x64
        int j = idx - 8192;
        int nn = j & 63, kp = j >> 6;
        float w0 = W2[(size_t)(2 * kp)     * 64 + nn];
        float w1 = W2[(size_t)(2 * kp + 1) * 64 + nn];
        *(__half2*)(g_w2t + nn * 128 + 2 * kp) = __floats2half2_rn(w0, w1);
    }
}

// -------------------- CSR: histogram + per-edge uint8 slot ------------------
__global__ void k_count(const int* __restrict__ dst, int e) {
    int i4 = (blockIdx.x * blockDim.x + threadIdx.x) * 4;
    if (i4 + 3 < e) {
        int4 d = *(const int4*)(dst + i4);
        uchar4 sl;
        sl.x = (uint8_t)atomicAdd(&g_cnt[d.x], 1);
        sl.y = (uint8_t)atomicAdd(&g_cnt[d.y], 1);
        sl.z = (uint8_t)atomicAdd(&g_cnt[d.z], 1);
        sl.w = (uint8_t)atomicAdd(&g_cnt[d.w], 1);
        *(uchar4*)(g_slot8 + i4) = sl;
    } else {
        for (int j = i4; j < e; j++)
            g_slot8[j] = (uint8_t)atomicAdd(&g_cnt[dst[j]], 1);
    }
}

// -------------------- CSR: single-pass scan (decoupled lookback) -----------
__global__ void __launch_bounds__(256)
k_scan_lb(int n, int nb) {
    __shared__ int warpsum[8];
    __shared__ int sh_total, sh_pref;
    const int b    = blockIdx.x;
    const int tid  = threadIdx.x;
    const int lane = tid & 31;
    const int w    = tid >> 5;
    const int idx  = b * 256 + tid;
    unsigned* st = (unsigned*)(g_cnt + NNODES);

    int x = (idx < n) ? g_cnt[idx] : 0;
    if (idx < n) g_dis[idx] = rsqrtf((float)(x + 1));

    int incl = x;
    #pragma unroll
    for (int o = 1; o < 32; o <<= 1) {
        int t = __shfl_up_sync(0xffffffffu, incl, o);
        if (lane >= o) incl += t;
    }
    if (lane == 31) warpsum[w] = incl;
    __syncthreads();
    if (w == 0) {
        int s = (lane < 8) ? warpsum[lane] : 0;
        #pragma unroll
        for (int o = 1; o < 8; o <<= 1) {
            int t = __shfl_up_sync(0xffffffffu, s, o);
            if (lane >= o) s += t;
        }
        if (lane < 8) warpsum[lane] = s;
    }
    __syncthreads();
    if (w > 0) incl += warpsum[w - 1];

    if (tid == 255) sh_total = incl;
    __syncthreads();

    if (tid == 255) {
        unsigned v = ((b == 0) ? SCAN_PRE : SCAN_AGG) | (unsigned)sh_total;
        __threadfence();
        atomicExch(&st[b], v);
    }
    if (tid == 0) {
        int run = 0;
        if (b > 0) {
            int p = b - 1;
            while (true) {
                unsigned s;
                do { s = atomicAdd(&st[p], 0u); } while ((s >> 30) == 0u);
                run += (int)(s & SCAN_VAL);
                if (s & SCAN_PRE) break;
                p--;
            }
            __threadfence();
            atomicExch(&st[b], SCAN_PRE | (unsigned)(run + sh_total));
        }
        sh_pref = run;
    }
    __syncthreads();

    int pre = sh_pref;
    if (idx < n) g_rowptr[idx] = pre + incl - x;
    if (idx == n - 1) g_rowptr[n] = pre + incl;
}

// -------------------- CSR: fill (atomic-free, 4 edges/thread) --------------
__global__ void k_fill(const int* __restrict__ src, const int* __restrict__ dst, int e) {
    int i4 = (blockIdx.x * blockDim.x + threadIdx.x) * 4;
    if (i4 + 3 < e) {
        int4 d  = *(const int4*)(dst + i4);
        int4 s  = *(const int4*)(src + i4);
        uchar4 sl = *(const uchar4*)(g_slot8 + i4);
        g_csr[g_rowptr[d.x] + sl.x] = s.x;
        g_csr[g_rowptr[d.y] + sl.y] = s.y;
        g_csr[g_rowptr[d.z] + sl.z] = s.z;
        g_csr[g_rowptr[d.w] + sl.w] = s.w;
    } else {
        for (int j = i4; j < e; j++)
            g_csr[g_rowptr[dst[j]] + (int)g_slot8[j]] = src[j];
    }
}

// -------------------- GEMM 1 (fp16 mma + ldmatrix): hs1 = (X@W1)*dis -------
#define SH_STRIDE 136
#define G1_SMEM ((128 * SH_STRIDE + 128 * SH_STRIDE) * 2)

__global__ void __launch_bounds__(256)
k_gemm1_mma(const float* __restrict__ X, int m) {
    extern __shared__ __half sh[];
    __half* As = sh;                       // [128][136]
    __half* Bs = sh + 128 * SH_STRIDE;     // [128][136]
    const int tid  = threadIdx.x;
    const int lane = tid & 31;
    const int wid  = tid >> 5;
    const int gr   = lane >> 2;
    const int gc   = lane & 3;
    const int bm   = blockIdx.x * 128;
    const int m0   = (wid & 3) * 32;
    const int n0   = (wid >> 2) * 64;

    #pragma unroll
    for (int i = 0; i < 8; i++) {
        int f = tid + i * 256;
        int r = f >> 4, c8 = (f & 15) * 8;
        float4 v0 = make_float4(0.f, 0.f, 0.f, 0.f);
        float4 v1 = v0;
        if (bm + r < m) {
            const float* xp = X + (size_t)(bm + r) * 128 + c8;
            v0 = *(const float4*)(xp);
            v1 = *(const float4*)(xp + 4);
        }
        __half2 h0 = __floats2half2_rn(v0.x, v0.y);
        __half2 h1 = __floats2half2_rn(v0.z, v0.w);
        __half2 h2 = __floats2half2_rn(v1.x, v1.y);
        __half2 h3 = __floats2half2_rn(v1.z, v1.w);
        uint4 u;
        u.x = *(uint32_t*)&h0; u.y = *(uint32_t*)&h1;
        u.z = *(uint32_t*)&h2; u.w = *(uint32_t*)&h3;
        *(uint4*)(As + r * SH_STRIDE + c8) = u;
    }
    #pragma unroll
    for (int i = 0; i < 8; i++) {
        int f = tid + i * 256;
        int r = f >> 4, c8 = (f & 15) * 8;
        *(uint4*)(Bs + r * SH_STRIDE + c8) = *(const uint4*)(g_w1t + r * 128 + c8);
    }
    __syncthreads();

    const uint32_t as_b = (uint32_t)__cvta_generic_to_shared(As);
    const uint32_t bs_b = (uint32_t)__cvta_generic_to_shared(Bs);
    const uint32_t a_row  = (uint32_t)(m0 + (lane & 15));
    const uint32_t a_koff = (uint32_t)((lane >> 4) << 3);
    const uint32_t a_ad0  = as_b + (a_row * SH_STRIDE + a_koff) * 2;
    const uint32_t a_ad1  = a_ad0 + 16 * SH_STRIDE * 2;
    const uint32_t b_row  = (uint32_t)(n0 + ((lane >> 4) << 3) + (lane & 7));
    const uint32_t b_koff = (uint32_t)(((lane >> 3) & 1) << 3);
    uint32_t b_ad[4];
    #pragma unroll
    for (int q = 0; q < 4; q++)
        b_ad[q] = bs_b + ((b_row + 16 * q) * SH_STRIDE + b_koff) * 2;

    float acc[2][8][4];
    #pragma unroll
    for (int a = 0; a < 2; a++)
        #pragma unroll
        for (int j = 0; j < 8; j++)
            #pragma unroll
            for (int q = 0; q < 4; q++) acc[a][j][q] = 0.f;

    #pragma unroll
    for (int ks = 0; ks < 8; ks++) {
        const uint32_t kb2 = ks * 32;
        uint32_t a0[4], a1[4], bq[4][4];
        LDSM4(a0, a_ad0 + kb2);
        LDSM4(a1, a_ad1 + kb2);
        #pragma unroll
        for (int q = 0; q < 4; q++) LDSM4(bq[q], b_ad[q] + kb2);
        #pragma unroll
        for (int j = 0; j < 8; j++) {
            int q = j >> 1, h = (j & 1) * 2;
            mma_f16(acc[0][j], a0, bq[q][h], bq[q][h + 1]);
            mma_f16(acc[1][j], a1, bq[q][h], bq[q][h + 1]);
        }
    }

    #pragma unroll
    for (int mf = 0; mf < 2; mf++) {
        int r0 = bm + m0 + mf * 16 + gr;
        int r1 = r0 + 8;
        float d0 = (r0 < m) ? g_dis[r0] : 0.f;
        float d1 = (r1 < m) ? g_dis[r1] : 0.f;
        #pragma unroll
        for (int j = 0; j < 8; j++) {
            int col = n0 + j * 8 + gc * 2;
            if (r0 < m)
                *(__half2*)(g_hs1 + (size_t)r0 * 128 + col) =
                    __floats2half2_rn(acc[mf][j][0] * d0, acc[mf][j][1] * d0);
            if (r1 < m)
                *(__half2*)(g_hs1 + (size_t)r1 * 128 + col) =
                    __floats2half2_rn(acc[mf][j][2] * d1, acc[mf][j][3] * d1);
        }
    }
}

// -------------------- GEMM 2 (fp16 mma + ldmatrix): hs2 = (x2@W2)*dis ------
#define G2_SMEM ((128 * SH_STRIDE + 64 * SH_STRIDE) * 2)

__global__ void __launch_bounds__(256)
k_gemm2_mma(int m) {
    extern __shared__ __half sh[];
    __half* As = sh;                       // [128][136]
    __half* Bs = sh + 128 * SH_STRIDE;     // [64][136]
    const int tid  = threadIdx.x;
    const int lane = tid & 31;
    const int wid  = tid >> 5;
    const int gr   = lane >> 2;
    const int gc   = lane & 3;
    const int bm   = blockIdx.x * 128;
    const int m0   = (wid & 3) * 32;
    const int n0   = (wid >> 2) * 32;

    #pragma unroll
    for (int i = 0; i < 8; i++) {
        int f = tid + i * 256;
        int r = f >> 4, c8 = (f & 15) * 8;
        uint4 v = make_uint4(0u, 0u, 0u, 0u);
        if (bm + r < m) v = *(const uint4*)(g_x2 + (size_t)(bm + r) * 128 + c8);
        *(uint4*)(As + r * SH_STRIDE + c8) = v;
    }
    #pragma unroll
    for (int i = 0; i < 4; i++) {
        int f = tid + i * 256;
        int r = f >> 4, c8 = (f & 15) * 8;
        *(uint4*)(Bs + r * SH_STRIDE + c8) = *(const uint4*)(g_w2t + r * 128 + c8);
    }
    __syncthreads();

    const uint32_t as_b = (uint32_t)__cvta_generic_to_shared(As);
    const uint32_t bs_b = (uint32_t)__cvta_generic_to_shared(Bs);
    const uint32_t a_row  = (uint32_t)(m0 + (lane & 15));
    const uint32_t a_koff = (uint32_t)((lane >> 4) << 3);
    const uint32_t a_ad0  = as_b + (a_row * SH_STRIDE + a_koff) * 2;
    const uint32_t a_ad1  = a_ad0 + 16 * SH_STRIDE * 2;
    const uint32_t b_row  = (uint32_t)(n0 + ((lane >> 4) << 3) + (lane & 7));
    const uint32_t b_koff = (uint32_t)(((lane >> 3) & 1) << 3);
    uint32_t b_ad[2];
    #pragma unroll
    for (int q = 0; q < 2; q++)
        b_ad[q] = bs_b + ((b_row + 16 * q) * SH_STRIDE + b_koff) * 2;

    float acc[2][4][4];
    #pragma unroll
    for (int a = 0; a < 2; a++)
        #pragma unroll
        for (int j = 0; j < 4; j++)
            #pragma unroll
            for (int q = 0; q < 4; q++) acc[a][j][q] = 0.f;

    #pragma unroll
    for (int ks = 0; ks < 8; ks++) {
        const uint32_t kb2 = ks * 32;
        uint32_t a0[4], a1[4], bq[2][4];
        LDSM4(a0, a_ad0 + kb2);
        LDSM4(a1, a_ad1 + kb2);
        #pragma unroll
        for (int q = 0; q < 2; q++) LDSM4(bq[q], b_ad[q] + kb2);
        #pragma unroll
        for (int j = 0; j < 4; j++) {
            int q = j >> 1, h = (j & 1) * 2;
            mma_f16(acc[0][j], a0, bq[q][h], bq[q][h + 1]);
            mma_f16(acc[1][j], a1, bq[q][h], bq[q][h + 1]);
        }
    }

    #pragma unroll
    for (int mf = 0; mf < 2; mf++) {
        int r0 = bm + m0 + mf * 16 + gr;
        int r1 = r0 + 8;
        float d0 = (r0 < m) ? g_dis[r0] : 0.f;
        float d1 = (r1 < m) ? g_dis[r1] : 0.f;
        #pragma unroll
        for (int j = 0; j < 4; j++) {
            int col = n0 + j * 8 + gc * 2;
            if (r0 < m)
                *(__half2*)(g_hs2 + (size_t)r0 * 64 + col) =
                    __floats2half2_rn(acc[mf][j][0] * d0, acc[mf][j][1] * d0);
            if (r1 < m)
                *(__half2*)(g_hs2 + (size_t)r1 * 64 + col) =
                    __floats2half2_rn(acc[mf][j][2] * d1, acc[mf][j][3] * d1);
        }
    }
}

// -------------------- Aggregation 1: x2 = relu(dis*(hs1[v]+sum)+b1) --------
// warp per node; 4-deep fp16 tree pre-add, fp32 accumulation.
__global__ void k_agg1(const float* __restrict__ b1, int n) {
    int v = (blockIdx.x * blockDim.x + threadIdx.x) >> 5;
    if (v >= n) return;
    int lane = threadIdx.x & 31;
    int c = lane * 4;
    int s0 = g_rowptr[v], s1 = g_rowptr[v + 1];

    const __half* base = g_hs1 + c;
    uint2 us = *(const uint2*)(base + (size_t)v * 128);
    float2 f01 = __half22float2(*(__half2*)&us.x);
    float2 f23 = __half22float2(*(__half2*)&us.y);
    float4 acc0 = make_float4(f01.x, f01.y, f23.x, f23.y);

    for (int j = s0; j < s1; j += 32) {
        int mm = s1 - j; if (mm > 32) mm = 32;
        int sv = (lane < mm) ? g_csr[j + lane] : 0;
        int t = 0;
        for (; t + 3 < mm; t += 4) {
            int i0 = __shfl_sync(0xffffffffu, sv, t);
            int i1 = __shfl_sync(0xffffffffu, sv, t + 1);
            int i2 = __shfl_sync(0xffffffffu, sv, t + 2);
            int i3 = __shfl_sync(0xffffffffu, sv, t + 3);
            uint2 u0 = *(const uint2*)(base + (size_t)i0 * 128);
            uint2 u1 = *(const uint2*)(base + (size_t)i1 * 128);
            uint2 u2 = *(const uint2*)(base + (size_t)i2 * 128);
            uint2 u3 = *(const uint2*)(base + (size_t)i3 * 128);
            __half2 p0 = __hadd2(*(__half2*)&u0.x, *(__half2*)&u1.x);
            __half2 p1 = __hadd2(*(__half2*)&u0.y, *(__half2*)&u1.y);
            __half2 p2 = __hadd2(*(__half2*)&u2.x, *(__half2*)&u3.x);
            __half2 p3 = __hadd2(*(__half2*)&u2.y, *(__half2*)&u3.y);
            __half2 q0 = __hadd2(p0, p2);              // 4-deep fp16 tree
            __half2 q1 = __hadd2(p1, p3);
            float2 a0 = __half22float2(q0);
            float2 a1 = __half22float2(q1);
            acc0.x += a0.x; acc0.y += a0.y; acc0.z += a1.x; acc0.w += a1.y;
        }
        if (t + 1 < mm) {
            int i0 = __shfl_sync(0xffffffffu, sv, t);
            int i1 = __shfl_sync(0xffffffffu, sv, t + 1);
            uint2 u0 = *(const uint2*)(base + (size_t)i0 * 128);
            uint2 u1 = *(const uint2*)(base + (size_t)i1 * 128);
            __half2 p0 = __hadd2(*(__half2*)&u0.x, *(__half2*)&u1.x);
            __half2 p1 = __hadd2(*(__half2*)&u0.y, *(__half2*)&u1.y);
            float2 a0 = __half22float2(p0);
            float2 a1 = __half22float2(p1);
            acc0.x += a0.x; acc0.y += a0.y; acc0.z += a1.x; acc0.w += a1.y;
            t += 2;
        }
        if (t < mm) {
            int i0 = __shfl_sync(0xffffffffu, sv, t);
            uint2 u0 = *(const uint2*)(base + (size_t)i0 * 128);
            float2 a = __half22float2(*(__half2*)&u0.x);
            float2 b = __half22float2(*(__half2*)&u0.y);
            acc0.x += a.x; acc0.y += a.y; acc0.z += b.x; acc0.w += b.y;
        }
    }
    float dv = g_dis[v];
    float4 bb = *(const float4*)(b1 + c);
    float ox = fmaxf(fmaf(dv, acc0.x, bb.x), 0.f);
    float oy = fmaxf(fmaf(dv, acc0.y, bb.y), 0.f);
    float oz = fmaxf(fmaf(dv, acc0.z, bb.z), 0.f);
    float ow = fmaxf(fmaf(dv, acc0.w, bb.w), 0.f);
    __half2 h01 = __floats2half2_rn(ox, oy);
    __half2 h23 = __floats2half2_rn(oz, ow);
    uint2 pk;
    pk.x = *(uint32_t*)&h01;
    pk.y = *(uint32_t*)&h23;
    *(uint2*)(g_x2 + (size_t)v * 128 + c) = pk;
}

// -------------------- Aggregation 2: out = dis*(hs2[v]+sum)+b2 -------------
__global__ void k_agg2(const float* __restrict__ b2, float* __restrict__ out, int n) {
    int v = (blockIdx.x * blockDim.x + threadIdx.x) >> 5;
    if (v >= n) return;
    int lane = threadIdx.x & 31;
    int c = lane * 2;
    int s0 = g_rowptr[v], s1 = g_rowptr[v + 1];

    const __half* base = g_hs2 + c;
    float2 acc0 = __half22float2(*(const __half2*)(base + (size_t)v * 64));

    for (int j = s0; j < s1; j += 32) {
        int mm = s1 - j; if (mm > 32) mm = 32;
        int sv = (lane < mm) ? g_csr[j + lane] : 0;
        int t = 0;
        for (; t + 3 < mm; t += 4) {
            int i0 = __shfl_sync(0xffffffffu, sv, t);
            int i1 = __shfl_sync(0xffffffffu, sv, t + 1);
            int i2 = __shfl_sync(0xffffffffu, sv, t + 2);
            int i3 = __shfl_sync(0xffffffffu, sv, t + 3);
            __half2 h0 = *(const __half2*)(base + (size_t)i0 * 64);
            __half2 h1 = *(const __half2*)(base + (size_t)i1 * 64);
            __half2 h2 = *(const __half2*)(base + (size_t)i2 * 64);
            __half2 h3 = *(const __half2*)(base + (size_t)i3 * 64);
            __half2 q = __hadd2(__hadd2(h0, h1), __hadd2(h2, h3));
            float2 a0 = __half22float2(q);
            acc0.x += a0.x; acc0.y += a0.y;
        }
        if (t + 1 < mm) {
            int i0 = __shfl_sync(0xffffffffu, sv, t);
            int i1 = __shfl_sync(0xffffffffu, sv, t + 1);
            __half2 h0 = *(const __half2*)(base + (size_t)i0 * 64);
            __half2 h1 = *(const __half2*)(base + (size_t)i1 * 64);
            float2 a0 = __half22float2(__hadd2(h0, h1));
            acc0.x += a0.x; acc0.y += a0.y;
            t += 2;
        }
        if (t < mm) {
            int i0 = __shfl_sync(0xffffffffu, sv, t);
            float2 h0 = __half22float2(*(const __half2*)(base + (size_t)i0 * 64));
            acc0.x += h0.x; acc0.y += h0.y;
        }
    }
    float dv = g_dis[v];
    float2 bb = *(const float2*)(b2 + c);
    float2 o;
    o.x = fmaf(dv, acc0.x, bb.x);
    o.y = fmaf(dv, acc0.y, bb.y);
    *(float2*)(out + (size_t)v * 64 + c) = o;
}

// -------------------- launch ------------------------------------------------
extern "C" void kernel_launch(void* const* d_in, const int* in_sizes, int n_in,
                              void* d_out, int out_size) {
    const float* x  = (const float*)d_in[0];
    const int*   ei = (const int*)d_in[1];
    const float* W1 = (const float*)d_in[2];
    const float* b1 = (const float*)d_in[3];
    const float* W2 = (const float*)d_in[4];
    const float* b2 = (const float*)d_in[5];
    float* out = (float*)d_out;

    const int n = in_sizes[0] / INC;   // 100000
    const int e = in_sizes[1] / 2;     // 1600000
    const int* src = ei;
    const int* dst = ei + e;

    const int nb_n  = (n + 255) / 256;    // scan blocks (391)
    const int nb_e4 = (e + 1023) / 1024;  // 4-edge/thread blocks (1563)

    static cudaStream_t s_side = nullptr;
    static cudaEvent_t ev_start = nullptr, ev_wt = nullptr,
                       ev_fork = nullptr, ev_join = nullptr;
    if (!s_side) {
        cudaStreamCreateWithFlags(&s_side, cudaStreamNonBlocking);
        cudaEventCreateWithFlags(&ev_start, cudaEventDisableTiming);
        cudaEventCreateWithFlags(&ev_wt,    cudaEventDisableTiming);
        cudaEventCreateWithFlags(&ev_fork,  cudaEventDisableTiming);
        cudaEventCreateWithFlags(&ev_join,  cudaEventDisableTiming);
        cudaFuncSetAttribute(k_gemm1_mma,
                             cudaFuncAttributeMaxDynamicSharedMemorySize, G1_SMEM);
        cudaFuncSetAttribute(k_gemm2_mma,
                             cudaFuncAttributeMaxDynamicSharedMemorySize, G2_SMEM);
    }

    // side stream: weight transpose overlapped with memset/count
    cudaEventRecord(ev_start, 0);
    cudaStreamWaitEvent(s_side, ev_start, 0);
    k_wt<<<48, 256, 0, s_side>>>(W1, W2);
    cudaEventRecord(ev_wt, s_side);

    // main: zero counts+states -> histogram(+uint8 slots) -> scan
    void* cnt_addr = nullptr;
    cudaGetSymbolAddress(&cnt_addr, g_cnt);
    cudaMemsetAsync(cnt_addr, 0, (size_t)(n + 512) * sizeof(int));
    k_count<<<nb_e4, 256>>>(dst, e);
    k_scan_lb<<<nb_n, 256>>>(n, nb_n);

    // fork: atomic-free CSR fill on side stream overlapped with gemm1
    cudaEventRecord(ev_fork, 0);
    cudaStreamWaitEvent(s_side, ev_fork, 0);
    k_fill<<<nb_e4, 256, 0, s_side>>>(src, dst, e);
    cudaEventRecord(ev_join, s_side);

    cudaStreamWaitEvent(0, ev_wt, 0);
    k_gemm1_mma<<<(n + 127) / 128, 256, G1_SMEM>>>(x, n);
    cudaStreamWaitEvent(0, ev_join, 0);

    k_agg1<<<(n + 7) / 8, 256>>>(b1, n);
    k_gemm2_mma<<<(n + 127) / 128, 256, G2_SMEM>>>(n);
    k_agg2<<<(n + 7) / 8, 256>>>(b2, out, n);
}